// round 2
// baseline (speedup 1.0000x reference)
#include <cuda_runtime.h>
#include <cstdint>

// WeightedFeatureInteraction: out[b] = sum_{i<j} w[i,j] * <x[b,i,:], x[b,j,:]>
//   inputs: [B, F*D] fp32, F=64, D=128;  field_weights: [F,F] fp32;  out: [B,1] fp32
//
// Round 2: LDS.128 of pre-duplicated weight pairs -> 1 smem wavefront per
// 2 FFMA2s, removing the LDS crossbar bottleneck (was 1 LDS.64 per FFMA2).

#define NF 64
#define ND 128
#define THREADS 128

typedef unsigned long long u64;

__device__ __forceinline__ u64 ffma2(u64 a, u64 b, u64 c) {
    u64 d;
    asm("fma.rn.f32x2 %0, %1, %2, %3;" : "=l"(d) : "l"(a), "l"(b), "l"(c));
    return d;
}

__device__ __forceinline__ u64 fadd2(u64 a, u64 b) {
    u64 d;
    asm("add.rn.f32x2 %0, %1, %2;" : "=l"(d) : "l"(a), "l"(b));
    return d;
}

__device__ __forceinline__ u64 bcast2(float x) {
    u64 d;
    asm("mov.b64 %0, {%1, %1};" : "=l"(d) : "f"(x));
    return d;
}

__global__ void __launch_bounds__(THREADS, 3)
wfi_kernel(const float* __restrict__ inputs,
           const float* __restrict__ fw,
           float* __restrict__ out) {
    // ws2[i][p] = { {w[i][2p], w[i][2p]}, {w[i][2p+1], w[i][2p+1]} }, masked j>i.
    __shared__ ulonglong2 ws2[NF][NF / 2];   // 32 KB
    __shared__ float red[4];

    const int tid = threadIdx.x;

    // Build masked, duplicated weight pairs in smem.
    for (int idx = tid; idx < NF * NF / 2; idx += THREADS) {
        int i = idx >> 5;          // row
        int p = idx & 31;          // pair
        int j0 = 2 * p, j1 = 2 * p + 1;
        float w0 = (j0 > i) ? fw[i * NF + j0] : 0.0f;
        float w1 = (j1 > i) ? fw[i * NF + j1] : 0.0f;
        ulonglong2 q;
        q.x = bcast2(w0);
        q.y = bcast2(w1);
        ws2[i][p] = q;
    }
    __syncthreads();

    const int b = blockIdx.x * 2 + (tid >> 6);   // batch row
    const int p = tid & 63;                      // d-pair (d = 2p, 2p+1)

    const float* xb = inputs + (size_t)b * (NF * ND) + 2 * p;

    // v[j] = (x[b,j,2p], x[b,j,2p+1]) -- coalesced 64-bit loads across lanes.
    u64 v[NF];
#pragma unroll
    for (int j = 0; j < NF; ++j) {
        v[j] = *(const u64*)(xb + j * ND);
    }

    // acc = sum_i v_i * (sum_{j>i} w_ij v_j); inner sum via LDS.128 pairs,
    // two interleaved FFMA2 chains. Zero-masked elements absorb misalignment.
    u64 acc = 0ull;
#pragma unroll
    for (int i = 0; i < NF - 1; ++i) {
        u64 t0 = 0ull, t1 = 0ull;
        const int p0 = (i + 1) >> 1;   // first pair containing a j > i
#pragma unroll
        for (int pp = p0; pp < NF / 2; ++pp) {
            ulonglong2 q = ws2[i][pp];
            t0 = ffma2(q.x, v[2 * pp], t0);
            t1 = ffma2(q.y, v[2 * pp + 1], t1);
        }
        acc = ffma2(v[i], fadd2(t0, t1), acc);
    }

    // Horizontal reduce: f32x2 halves, then 64 threads per batch row.
    float2 a2 = *(float2*)&acc;
    float s = a2.x + a2.y;
#pragma unroll
    for (int off = 16; off > 0; off >>= 1)
        s += __shfl_xor_sync(0xFFFFFFFFu, s, off);

    const int wid = tid >> 5;
    if ((tid & 31) == 0) red[wid] = s;
    __syncthreads();

    if (tid == 0)  out[b] = red[0] + red[1];
    if (tid == 64) out[b] = red[2] + red[3];
}

extern "C" void kernel_launch(void* const* d_in, const int* in_sizes, int n_in,
                              void* d_out, int out_size) {
    const float* inputs = (const float*)d_in[0];
    const float* fw     = (const float*)d_in[1];
    float* out          = (float*)d_out;

    int B = in_sizes[0] / (NF * ND);
    wfi_kernel<<<B / 2, THREADS>>>(inputs, fw, out);
}